// round 13
// baseline (speedup 1.0000x reference)
#include <cuda_runtime.h>
#include <cuda_bf16.h>
#include <cstdint>
#include <math.h>

// Problem constants
#define T_TOKENS 16384
#define HID      2880
#define NE       128
#define TOPK     4

// Tiling
#define MT       128              // tokens per block
#define KB       32               // K-tile depth (4 mma k-steps of 8)
#define THREADS  256              // 8 warps: 4 (M) x 2 (N), warp tile 32x64
#define NTILES   (HID / KB)       // 90
#define NKSTEP   (HID / 8)        // 360 global k-steps

// ---- smem layout (dynamic, bytes from base) ----
// stage s at s*69632:  A_hi [128 rows x 144B] at +0      (18432 B)
//                      A_lo                  at +18432   (18432 B)
//                      B frag-major          at +36864   (32768 B)
// Lg aliases stage0: float[128][129] = 66048 B
#define A_ROW    144
#define A_TERM   18432
#define B_OFF    36864
#define STAGE_SZ 69632
#define SM_TOPI  139264
#define SM_TOPP  141312
#define SMEM_BYTES 143360

// Fragment-major pre-split weight scratch: per global k-step S (360), n-tile t (16),
// lane l (32): 16B = { B_hi[k=c][n], B_hi[k=c+4][n], B_lo[c][n], B_lo[c+4][n] }
// with n = t*8 + (l>>2), c = l&3, k = S*8 + c.  Total 2.95 MB.
__device__ __align__(16) float g_Wfrag[NE * HID * 2];

// ---------------- helpers ----------------
__device__ __forceinline__ uint32_t smem_u32(const void* p) {
    uint32_t a;
    asm("{ .reg .u64 t; cvta.to.shared.u64 t, %1; cvt.u32.u64 %0, t; }" : "=r"(a) : "l"(p));
    return a;
}
__device__ __forceinline__ float tf32_rna(float x) {
    float r; asm("cvt.rna.tf32.f32 %0, %1;" : "=f"(r) : "f"(x)); return r;
}

#define CP_ASYNC16(dst, src) \
    asm volatile("cp.async.cg.shared.global [%0], [%1], 16;" :: "r"(dst), "l"(src))
#define CP_COMMIT()  asm volatile("cp.async.commit_group;")
#define CP_WAIT0()   asm volatile("cp.async.wait_group 0;")

#define STS128F(addr, a, b, c, d) \
    asm volatile("st.shared.v4.f32 [%0], {%1,%2,%3,%4};" :: "r"(addr), "f"(a), "f"(b), "f"(c), "f"(d) : "memory")
#define STS32F(addr, a) \
    asm volatile("st.shared.f32 [%0], %1;" :: "r"(addr), "f"(a) : "memory")
#define LDS32U(r, addr) \
    asm volatile("ld.shared.b32 %0, [%1];" : "=r"(r) : "r"(addr))
#define LDS128U(r0, r1, r2, r3, addr) \
    asm volatile("ld.shared.v4.b32 {%0,%1,%2,%3}, [%4];" : "=r"(r0), "=r"(r1), "=r"(r2), "=r"(r3) : "r"(addr))

// m16n8k8 tf32 mma (baseline PTX, works on plain sm_103 target via HMMA path)
#define MMA8(d, a, b0_, b1_)                                                  \
    asm volatile("mma.sync.aligned.m16n8k8.row.col.f32.tf32.tf32.f32 "        \
        "{%0,%1,%2,%3}, {%4,%5,%6,%7}, {%8,%9}, {%0,%1,%2,%3};"               \
        : "+f"((d)[0]), "+f"((d)[1]), "+f"((d)[2]), "+f"((d)[3])              \
        : "r"((a)[0]), "r"((a)[1]), "r"((a)[2]), "r"((a)[3]),                 \
          "r"(b0_), "r"(b1_))

// ---------------- prep: split W into tf32 hi/lo, fragment-major ----------------
__global__ void convert_w_frag(const float* __restrict__ W) {
    int idx = blockIdx.x * blockDim.x + threadIdx.x;     // (S, t, lane)
    if (idx < NKSTEP * 16 * 32) {
        const int lane = idx & 31;
        const int t    = (idx >> 5) & 15;
        const int S    = idx >> 9;
        const int gq   = lane >> 2, c = lane & 3;
        const int n    = t * 8 + gq;
        const int k0   = S * 8 + c;
        float w0 = W[(size_t)n * HID + k0];
        float w1 = W[(size_t)n * HID + k0 + 4];
        float h0 = tf32_rna(w0), h1 = tf32_rna(w1);
        float l0 = tf32_rna(w0 - h0), l1 = tf32_rna(w1 - h1);
        const int it = S >> 2, s = S & 3;
        float4* dst = (float4*)((char*)g_Wfrag +
                      (size_t)it * 32768 + (size_t)((s * 16 + t) * 32 + lane) * 16);
        *dst = make_float4(h0, h1, l0, l1);
    }
}

// ---------------- main fused kernel ----------------
extern __shared__ char dsm[];

__global__ __launch_bounds__(THREADS, 1)
void router_mma_kernel(const float* __restrict__ X,
                       const int*   __restrict__ mask,
                       const float* __restrict__ bias,
                       const float* __restrict__ vbias,
                       float* __restrict__ out,
                       int write_idx)
{
    const int tid  = threadIdx.x;
    const int wid  = tid >> 5;
    const int lane = tid & 31;
    const int wm   = wid & 3;          // warp M index (32 tokens)
    const int wn   = wid >> 2;         // warp N index (64 experts)
    const int g    = lane >> 2;
    const int c    = lane & 3;
    const int row0 = blockIdx.x * MT;
    const uint32_t sbase = smem_u32(dsm);

    float acc[2][8][4];
#pragma unroll
    for (int mt = 0; mt < 2; mt++)
#pragma unroll
        for (int t = 0; t < 8; t++)
#pragma unroll
            for (int r = 0; r < 4; r++) acc[mt][t][r] = 0.0f;

    // fill mapping: token fm = tid>>1, k-half fh = tid&1 (16 k each)
    const int fm = tid >> 1, fh = tid & 1;
    const float* Xp = X + (size_t)(row0 + fm) * HID + fh * 16;
    const uint32_t aFillBase = fm * A_ROW + fh * 64;     // byte offset within A_hi region
    const uint32_t bFillOff  = B_OFF + tid * 128;        // 128 B per thread per tile
    const char* wsrcBase = (const char*)g_Wfrag + (size_t)tid * 128;

    // ---- prologue: fill stage 0 ----
    {
#pragma unroll
        for (int j = 0; j < 8; j++)
            CP_ASYNC16(sbase + bFillOff + j * 16, wsrcBase + j * 16);
        CP_COMMIT();
#pragma unroll
        for (int j = 0; j < 4; j++) {
            float4 x = *(const float4*)(Xp + j * 4);
            float h0 = tf32_rna(x.x), h1 = tf32_rna(x.y);
            float h2 = tf32_rna(x.z), h3 = tf32_rna(x.w);
            STS128F(sbase + aFillBase + j * 16, h0, h1, h2, h3);
            STS128F(sbase + A_TERM + aFillBase + j * 16,
                    x.x - h0, x.y - h1, x.z - h2, x.w - h3);
        }
        CP_WAIT0();
        __syncthreads();
    }

    // ---- main loop: double-buffered, one barrier per K-tile ----
    for (int it = 0; it < NTILES; ++it) {
        const uint32_t cs = sbase + (it & 1) * STAGE_SZ;
        const uint32_t ns = sbase + ((it + 1) & 1) * STAGE_SZ;
        float4 xv[4];

        if (it + 1 < NTILES) {
            const float* xs = Xp + (it + 1) * KB;
#pragma unroll
            for (int j = 0; j < 4; j++) xv[j] = *(const float4*)(xs + j * 4);
            const char* bs = wsrcBase + (size_t)(it + 1) * 32768;
#pragma unroll
            for (int j = 0; j < 8; j++)
                CP_ASYNC16(ns + bFillOff + j * 16, bs + j * 16);
            CP_COMMIT();
        }

        // compute 4 k-steps from cur stage
        const uint32_t aB0 = cs + (uint32_t)(wm * 32 + g) * A_ROW + c * 4;
        const uint32_t bB0 = cs + B_OFF + (uint32_t)(wn * 8) * 512 + lane * 16;
#pragma unroll
        for (int s = 0; s < 4; s++) {
            uint32_t ah[2][4], al[2][4];
#pragma unroll
            for (int mt = 0; mt < 2; mt++) {
                const uint32_t b = aB0 + s * 32 + mt * 2304;
                LDS32U(ah[mt][0], b);
                LDS32U(ah[mt][1], b + 1152);
                LDS32U(ah[mt][2], b + 16);
                LDS32U(ah[mt][3], b + 1168);
                LDS32U(al[mt][0], b + A_TERM);
                LDS32U(al[mt][1], b + A_TERM + 1152);
                LDS32U(al[mt][2], b + A_TERM + 16);
                LDS32U(al[mt][3], b + A_TERM + 1168);
            }
            const uint32_t bb = bB0 + (uint32_t)(s * 16) * 512;
#pragma unroll
            for (int t = 0; t < 8; t++) {
                uint32_t bh0, bh1, bl0, bl1;
                LDS128U(bh0, bh1, bl0, bl1, bb + t * 512);
#pragma unroll
                for (int mt = 0; mt < 2; mt++) {
                    MMA8(acc[mt][t], ah[mt], bh0, bh1);   // hi * hi
                    MMA8(acc[mt][t], ah[mt], bl0, bl1);   // hi * lo
                    MMA8(acc[mt][t], al[mt], bh0, bh1);   // lo * hi
                }
            }
        }

        if (it + 1 < NTILES) {
#pragma unroll
            for (int j = 0; j < 4; j++) {
                float4 x = xv[j];
                float h0 = tf32_rna(x.x), h1 = tf32_rna(x.y);
                float h2 = tf32_rna(x.z), h3 = tf32_rna(x.w);
                STS128F(ns + aFillBase + j * 16, h0, h1, h2, h3);
                STS128F(ns + A_TERM + aFillBase + j * 16,
                        x.x - h0, x.y - h1, x.z - h2, x.w - h3);
            }
            CP_WAIT0();
        }
        __syncthreads();
    }

    // ---- epilogue: accumulators (+bias/vbias) -> Lg smem (aliases stage0) ----
    // NOTE: Lg row stride is 129 floats (516 B): odd rows are only 4-byte aligned,
    // so writes MUST be scalar st.shared.f32 (v2 traps with misaligned address).
    {
        int vm[4];
#pragma unroll
        for (int h = 0; h < 4; h++)
            vm[h] = mask[row0 + wm * 32 + h * 8 + g];   // rows g, g+8, g+16, g+24

#pragma unroll
        for (int t = 0; t < 8; t++) {
            const int C = wn * 64 + t * 8 + 2 * c;
            const float b0v = __ldg(bias + C),  b1v = __ldg(bias + C + 1);
            const float v0v = __ldg(vbias + C), v1v = __ldg(vbias + C + 1);
#pragma unroll
            for (int mt = 0; mt < 2; mt++) {
#pragma unroll
                for (int rh = 0; rh < 2; rh++) {
                    const int hidx = mt * 2 + rh;
                    const int R = wm * 32 + mt * 16 + rh * 8 + g;
                    const float va = acc[mt][t][rh * 2 + 0] + b0v + (vm[hidx] ? v0v : 0.0f);
                    const float vb = acc[mt][t][rh * 2 + 1] + b1v + (vm[hidx] ? v1v : 0.0f);
                    const uint32_t ad = sbase + (uint32_t)(R * (NE + 1) + C) * 4;
                    STS32F(ad, va);
                    STS32F(ad + 4, vb);
                }
            }
        }
    }
    __syncthreads();

    // ---- top-4 + softmax: one thread per token (128 of 256) ----
    int*   s_top_i = (int*)  (dsm + SM_TOPI);
    float* s_top_p = (float*)(dsm + SM_TOPP);
    if (tid < MT) {
        const int t = tid;
        const float* Lr = (const float*)dsm + (size_t)t * (NE + 1);
        float v0 = -INFINITY, v1 = -INFINITY, v2 = -INFINITY, v3 = -INFINITY;
        int   i0 = 0, i1 = 0, i2 = 0, i3 = 0;
#pragma unroll 8
        for (int e = 0; e < NE; e++) {
            float v = Lr[e];
            // strict '>' keeps earlier index ahead on ties, matching jax top_k
            if (v > v2) {
                if (v > v0)      { v3 = v2; i3 = i2; v2 = v1; i2 = i1; v1 = v0; i1 = i0; v0 = v; i0 = e; }
                else if (v > v1) { v3 = v2; i3 = i2; v2 = v1; i2 = i1; v1 = v; i1 = e; }
                else             { v3 = v2; i3 = i2; v2 = v; i2 = e; }
            } else if (v > v3)   { v3 = v; i3 = e; }
        }
        const float x1 = expf(v1 - v0);
        const float x2 = expf(v2 - v0);
        const float x3 = expf(v3 - v0);
        const float inv = 1.0f / (1.0f + x1 + x2 + x3);

        s_top_i[t * 4 + 0] = i0; s_top_i[t * 4 + 1] = i1;
        s_top_i[t * 4 + 2] = i2; s_top_i[t * 4 + 3] = i3;
        s_top_p[t * 4 + 0] = inv;      s_top_p[t * 4 + 1] = x1 * inv;
        s_top_p[t * 4 + 2] = x2 * inv; s_top_p[t * 4 + 3] = x3 * inv;

        if (write_idx) {
            float* io = out + (size_t)T_TOKENS * NE + (size_t)(row0 + t) * TOPK;
            io[0] = (float)i0; io[1] = (float)i1; io[2] = (float)i2; io[3] = (float)i3;
        }
    }
    __syncthreads();

    // ---- coalesced dense scatter: 128x128 tile, float4 per thread-iteration ----
    float4* out4 = (float4*)out;
    for (int q = tid; q < MT * NE / 4; q += THREADS) {
        const int t  = q >> 5;
        const int c4 = q & 31;
        const int e0 = c4 * 4;
        const int ti0 = s_top_i[t * 4 + 0], ti1 = s_top_i[t * 4 + 1];
        const int ti2 = s_top_i[t * 4 + 2], ti3 = s_top_i[t * 4 + 3];
        const float p0 = s_top_p[t * 4 + 0], p1 = s_top_p[t * 4 + 1];
        const float p2 = s_top_p[t * 4 + 2], p3 = s_top_p[t * 4 + 3];
        float4 o;
        float* of = (float*)&o;
#pragma unroll
        for (int j = 0; j < 4; j++) {
            const int e = e0 + j;
            float v = 0.0f;
            if (e == ti0) v = p0;
            else if (e == ti1) v = p1;
            else if (e == ti2) v = p2;
            else if (e == ti3) v = p3;
            of[j] = v;
        }
        out4[(size_t)(row0 + t) * (NE / 4) + c4] = o;
    }
}

extern "C" void kernel_launch(void* const* d_in, const int* in_sizes, int n_in,
                              void* d_out, int out_size)
{
    const float* X     = (const float*)d_in[0];   // (4,4096,2880) f32
    const int*   mask  = (const int*)  d_in[1];   // (4,4096) bool -> int32
    const float* W     = (const float*)d_in[2];   // (128,2880) f32
    const float* bias  = (const float*)d_in[3];   // (128,)
    const float* vbias = (const float*)d_in[4];   // (128,)
    float* out = (float*)d_out;

    // opt into >48KB dynamic smem (idempotent host-side attribute set)
    cudaFuncSetAttribute(router_mma_kernel,
                         cudaFuncAttributeMaxDynamicSharedMemorySize, SMEM_BYTES);

    // 1) split W into tf32 hi/lo fragment-major scratch (L2-resident, 3 MB)
    convert_w_frag<<<(NKSTEP * 16 * 32 + 255) / 256, 256>>>(W);

    // 2) fused 3xTF32 mma.sync GEMM + topk + softmax + scatter (single wave, 128 blocks)
    const int write_idx =
        (out_size >= T_TOKENS * NE + T_TOKENS * TOPK) ? 1 : 0;
    router_mma_kernel<<<T_TOKENS / MT, THREADS, SMEM_BYTES>>>(
        X, mask, bias, vbias, out, write_idx);
}

// round 14
// speedup vs baseline: 1.7837x; 1.7837x over previous
#include <cuda_runtime.h>
#include <cuda_bf16.h>
#include <cstdint>
#include <math.h>

// Problem constants
#define T_TOKENS 16384
#define HID      2880
#define NE       128
#define TOPK     4

// Tiling
#define MT       128              // tokens per block
#define KB       32               // K-tile depth (4 mma k-steps of 8)
#define THREADS  512              // 16 warps: 8 (M, 16 tokens each) x 2 (N, 64 experts)
#define NTILES   (HID / KB)       // 90
#define NKSTEP   (HID / 8)        // 360 global k-steps

// ---- smem layout (dynamic, bytes from base) ----
// stage s at s*69632:  A_hi [128 rows x 144B] at +0      (18432 B)
//                      A_lo                  at +18432   (18432 B)
//                      B frag-major          at +36864   (32768 B)
// Lg aliases stage0: float[128][129] = 66048 B
#define A_ROW    144
#define A_TERM   18432
#define B_OFF    36864
#define STAGE_SZ 69632
#define SM_TOPI  139264
#define SM_TOPP  141312
#define SMEM_BYTES 143360

// Fragment-major pre-split weight scratch: per global k-step S (360), n-tile t (16),
// lane l (32): 16B = { B_hi[k=c][n], B_hi[k=c+4][n], B_lo[c][n], B_lo[c+4][n] }
// with n = t*8 + (l>>2), c = l&3, k = S*8 + c.  Total 2.95 MB.
__device__ __align__(16) float g_Wfrag[NE * HID * 2];

// ---------------- helpers ----------------
__device__ __forceinline__ uint32_t smem_u32(const void* p) {
    uint32_t a;
    asm("{ .reg .u64 t; cvta.to.shared.u64 t, %1; cvt.u32.u64 %0, t; }" : "=r"(a) : "l"(p));
    return a;
}
__device__ __forceinline__ float tf32_rna(float x) {
    float r; asm("cvt.rna.tf32.f32 %0, %1;" : "=f"(r) : "f"(x)); return r;
}

#define CP_ASYNC16(dst, src) \
    asm volatile("cp.async.cg.shared.global [%0], [%1], 16;" :: "r"(dst), "l"(src))
#define CP_COMMIT()  asm volatile("cp.async.commit_group;")
#define CP_WAIT0()   asm volatile("cp.async.wait_group 0;")

#define STS128F(addr, a, b, c, d) \
    asm volatile("st.shared.v4.f32 [%0], {%1,%2,%3,%4};" :: "r"(addr), "f"(a), "f"(b), "f"(c), "f"(d) : "memory")
#define STS32F(addr, a) \
    asm volatile("st.shared.f32 [%0], %1;" :: "r"(addr), "f"(a) : "memory")
#define LDS32U(r, addr) \
    asm volatile("ld.shared.b32 %0, [%1];" : "=r"(r) : "r"(addr))
#define LDS128U(r0, r1, r2, r3, addr) \
    asm volatile("ld.shared.v4.b32 {%0,%1,%2,%3}, [%4];" : "=r"(r0), "=r"(r1), "=r"(r2), "=r"(r3) : "r"(addr))

// m16n8k8 tf32 mma (baseline PTX, HMMA path on plain sm_103 target)
#define MMA8(d, a, b0_, b1_)                                                  \
    asm volatile("mma.sync.aligned.m16n8k8.row.col.f32.tf32.tf32.f32 "        \
        "{%0,%1,%2,%3}, {%4,%5,%6,%7}, {%8,%9}, {%0,%1,%2,%3};"               \
        : "+f"((d)[0]), "+f"((d)[1]), "+f"((d)[2]), "+f"((d)[3])              \
        : "r"((a)[0]), "r"((a)[1]), "r"((a)[2]), "r"((a)[3]),                 \
          "r"(b0_), "r"(b1_))

// ---------------- prep: split W into tf32 hi/lo, fragment-major ----------------
__global__ void convert_w_frag(const float* __restrict__ W) {
    int idx = blockIdx.x * blockDim.x + threadIdx.x;     // (S, t, lane)
    if (idx < NKSTEP * 16 * 32) {
        const int lane = idx & 31;
        const int t    = (idx >> 5) & 15;
        const int S    = idx >> 9;
        const int gq   = lane >> 2, c = lane & 3;
        const int n    = t * 8 + gq;
        const int k0   = S * 8 + c;
        float w0 = W[(size_t)n * HID + k0];
        float w1 = W[(size_t)n * HID + k0 + 4];
        float h0 = tf32_rna(w0), h1 = tf32_rna(w1);
        float l0 = tf32_rna(w0 - h0), l1 = tf32_rna(w1 - h1);
        const int it = S >> 2, s = S & 3;
        float4* dst = (float4*)((char*)g_Wfrag +
                      (size_t)it * 32768 + (size_t)((s * 16 + t) * 32 + lane) * 16);
        *dst = make_float4(h0, h1, l0, l1);
    }
}

// ---------------- main fused kernel ----------------
extern __shared__ char dsm[];

__global__ __launch_bounds__(THREADS, 1)
void router_mma_kernel(const float* __restrict__ X,
                       const int*   __restrict__ mask,
                       const float* __restrict__ bias,
                       const float* __restrict__ vbias,
                       float* __restrict__ out,
                       int write_idx)
{
    const int tid  = threadIdx.x;
    const int wid  = tid >> 5;
    const int lane = tid & 31;
    const int wm   = wid & 7;          // warp M index (16 tokens each)
    const int wn   = wid >> 3;         // warp N index (64 experts each)
    const int g    = lane >> 2;
    const int c    = lane & 3;
    const int row0 = blockIdx.x * MT;
    const uint32_t sbase = smem_u32(dsm);

    float acc[8][4];
#pragma unroll
    for (int t = 0; t < 8; t++)
#pragma unroll
        for (int r = 0; r < 4; r++) acc[t][r] = 0.0f;

    // fill mapping: token fm = tid>>2 (0..127), quarter fq = tid&3 (8 floats each)
    const int fm = tid >> 2, fq = tid & 3;
    const float* Xp = X + (size_t)(row0 + fm) * HID + fq * 8;
    const uint32_t aFillBase = fm * A_ROW + fq * 32;     // byte offset within A_hi region
    const uint32_t bFillOff  = B_OFF + tid * 64;         // 64 B per thread per tile
    const char* wsrcBase = (const char*)g_Wfrag + (size_t)tid * 64;

    // ---- prologue: fill stage 0 ----
    {
#pragma unroll
        for (int j = 0; j < 4; j++)
            CP_ASYNC16(sbase + bFillOff + j * 16, wsrcBase + j * 16);
        CP_COMMIT();
#pragma unroll
        for (int j = 0; j < 2; j++) {
            float4 x = *(const float4*)(Xp + j * 4);
            float h0 = tf32_rna(x.x), h1 = tf32_rna(x.y);
            float h2 = tf32_rna(x.z), h3 = tf32_rna(x.w);
            STS128F(sbase + aFillBase + j * 16, h0, h1, h2, h3);
            STS128F(sbase + A_TERM + aFillBase + j * 16,
                    x.x - h0, x.y - h1, x.z - h2, x.w - h3);
        }
        CP_WAIT0();
        __syncthreads();
    }

    // ---- main loop: double-buffered, one barrier per K-tile ----
    for (int it = 0; it < NTILES; ++it) {
        const uint32_t cs = sbase + (it & 1) * STAGE_SZ;
        const uint32_t ns = sbase + ((it + 1) & 1) * STAGE_SZ;
        float4 xv[2];

        if (it + 1 < NTILES) {
            const float* xs = Xp + (it + 1) * KB;
#pragma unroll
            for (int j = 0; j < 2; j++) xv[j] = *(const float4*)(xs + j * 4);
            const char* bs = wsrcBase + (size_t)(it + 1) * 32768;
#pragma unroll
            for (int j = 0; j < 4; j++)
                CP_ASYNC16(ns + bFillOff + j * 16, bs + j * 16);
            CP_COMMIT();
        }

        // compute 4 k-steps from cur stage
        const uint32_t aB0 = cs + (uint32_t)(wm * 16 + g) * A_ROW + c * 4;
        const uint32_t bB0 = cs + B_OFF + (uint32_t)(wn * 8) * 512 + lane * 16;
#pragma unroll
        for (int s = 0; s < 4; s++) {
            uint32_t ah[4], al[4];
            {
                const uint32_t b = aB0 + s * 32;
                LDS32U(ah[0], b);
                LDS32U(ah[1], b + 1152);
                LDS32U(ah[2], b + 16);
                LDS32U(ah[3], b + 1168);
                LDS32U(al[0], b + A_TERM);
                LDS32U(al[1], b + A_TERM + 1152);
                LDS32U(al[2], b + A_TERM + 16);
                LDS32U(al[3], b + A_TERM + 1168);
            }
            const uint32_t bb = bB0 + (uint32_t)s * 8192;
#pragma unroll
            for (int t = 0; t < 8; t++) {
                uint32_t bh0, bh1, bl0, bl1;
                LDS128U(bh0, bh1, bl0, bl1, bb + t * 512);
                MMA8(acc[t], ah, bh0, bh1);   // hi * hi
                MMA8(acc[t], ah, bl0, bl1);   // hi * lo
                MMA8(acc[t], al, bh0, bh1);   // lo * hi
            }
        }

        if (it + 1 < NTILES) {
#pragma unroll
            for (int j = 0; j < 2; j++) {
                float4 x = xv[j];
                float h0 = tf32_rna(x.x), h1 = tf32_rna(x.y);
                float h2 = tf32_rna(x.z), h3 = tf32_rna(x.w);
                STS128F(ns + aFillBase + j * 16, h0, h1, h2, h3);
                STS128F(ns + A_TERM + aFillBase + j * 16,
                        x.x - h0, x.y - h1, x.z - h2, x.w - h3);
            }
            CP_WAIT0();
        }
        __syncthreads();
    }

    // ---- epilogue: accumulators (+bias/vbias) -> Lg smem (aliases stage0) ----
    // Lg row stride is 129 floats (516 B): odd rows only 4-byte aligned -> scalar STS.
    {
        const int vm0 = mask[row0 + wm * 16 + g];
        const int vm1 = mask[row0 + wm * 16 + 8 + g];

#pragma unroll
        for (int t = 0; t < 8; t++) {
            const int C = wn * 64 + t * 8 + 2 * c;
            const float b0v = __ldg(bias + C),  b1v = __ldg(bias + C + 1);
            const float v0v = __ldg(vbias + C), v1v = __ldg(vbias + C + 1);

            const int R0 = wm * 16 + g;
            const uint32_t ad0 = sbase + (uint32_t)(R0 * (NE + 1) + C) * 4;
            STS32F(ad0,     acc[t][0] + b0v + (vm0 ? v0v : 0.0f));
            STS32F(ad0 + 4, acc[t][1] + b1v + (vm0 ? v1v : 0.0f));

            const int R1 = R0 + 8;
            const uint32_t ad1 = sbase + (uint32_t)(R1 * (NE + 1) + C) * 4;
            STS32F(ad1,     acc[t][2] + b0v + (vm1 ? v0v : 0.0f));
            STS32F(ad1 + 4, acc[t][3] + b1v + (vm1 ? v1v : 0.0f));
        }
    }
    __syncthreads();

    // ---- top-4 + softmax: one thread per token (128 of 512) ----
    int*   s_top_i = (int*)  (dsm + SM_TOPI);
    float* s_top_p = (float*)(dsm + SM_TOPP);
    if (tid < MT) {
        const int t = tid;
        const float* Lr = (const float*)dsm + (size_t)t * (NE + 1);
        float v0 = -INFINITY, v1 = -INFINITY, v2 = -INFINITY, v3 = -INFINITY;
        int   i0 = 0, i1 = 0, i2 = 0, i3 = 0;
#pragma unroll 8
        for (int e = 0; e < NE; e++) {
            float v = Lr[e];
            // strict '>' keeps earlier index ahead on ties, matching jax top_k
            if (v > v2) {
                if (v > v0)      { v3 = v2; i3 = i2; v2 = v1; i2 = i1; v1 = v0; i1 = i0; v0 = v; i0 = e; }
                else if (v > v1) { v3 = v2; i3 = i2; v2 = v1; i2 = i1; v1 = v; i1 = e; }
                else             { v3 = v2; i3 = i2; v2 = v; i2 = e; }
            } else if (v > v3)   { v3 = v; i3 = e; }
        }
        const float x1 = expf(v1 - v0);
        const float x2 = expf(v2 - v0);
        const float x3 = expf(v3 - v0);
        const float inv = 1.0f / (1.0f + x1 + x2 + x3);

        s_top_i[t * 4 + 0] = i0; s_top_i[t * 4 + 1] = i1;
        s_top_i[t * 4 + 2] = i2; s_top_i[t * 4 + 3] = i3;
        s_top_p[t * 4 + 0] = inv;      s_top_p[t * 4 + 1] = x1 * inv;
        s_top_p[t * 4 + 2] = x2 * inv; s_top_p[t * 4 + 3] = x3 * inv;

        if (write_idx) {
            float* io = out + (size_t)T_TOKENS * NE + (size_t)(row0 + t) * TOPK;
            io[0] = (float)i0; io[1] = (float)i1; io[2] = (float)i2; io[3] = (float)i3;
        }
    }
    __syncthreads();

    // ---- coalesced dense scatter: 128x128 tile, float4 per thread-iteration ----
    float4* out4 = (float4*)out;
    for (int q = tid; q < MT * NE / 4; q += THREADS) {
        const int t  = q >> 5;
        const int c4 = q & 31;
        const int e0 = c4 * 4;
        const int ti0 = s_top_i[t * 4 + 0], ti1 = s_top_i[t * 4 + 1];
        const int ti2 = s_top_i[t * 4 + 2], ti3 = s_top_i[t * 4 + 3];
        const float p0 = s_top_p[t * 4 + 0], p1 = s_top_p[t * 4 + 1];
        const float p2 = s_top_p[t * 4 + 2], p3 = s_top_p[t * 4 + 3];
        float4 o;
        float* of = (float*)&o;
#pragma unroll
        for (int j = 0; j < 4; j++) {
            const int e = e0 + j;
            float v = 0.0f;
            if (e == ti0) v = p0;
            else if (e == ti1) v = p1;
            else if (e == ti2) v = p2;
            else if (e == ti3) v = p3;
            of[j] = v;
        }
        out4[(size_t)(row0 + t) * (NE / 4) + c4] = o;
    }
}

extern "C" void kernel_launch(void* const* d_in, const int* in_sizes, int n_in,
                              void* d_out, int out_size)
{
    const float* X     = (const float*)d_in[0];   // (4,4096,2880) f32
    const int*   mask  = (const int*)  d_in[1];   // (4,4096) bool -> int32
    const float* W     = (const float*)d_in[2];   // (128,2880) f32
    const float* bias  = (const float*)d_in[3];   // (128,)
    const float* vbias = (const float*)d_in[4];   // (128,)
    float* out = (float*)d_out;

    // opt into >48KB dynamic smem (idempotent host-side attribute set)
    cudaFuncSetAttribute(router_mma_kernel,
                         cudaFuncAttributeMaxDynamicSharedMemorySize, SMEM_BYTES);

    // 1) split W into tf32 hi/lo fragment-major scratch (L2-resident, 3 MB)
    convert_w_frag<<<(NKSTEP * 16 * 32 + 255) / 256, 256>>>(W);

    // 2) fused 3xTF32 mma.sync GEMM + topk + softmax + scatter
    //    16 warps/CTA (4 per SMSP) to cover mma.sync latency
    const int write_idx =
        (out_size >= T_TOKENS * NE + T_TOKENS * TOPK) ? 1 : 0;
    router_mma_kernel<<<T_TOKENS / MT, THREADS, SMEM_BYTES>>>(
        X, mask, bias, vbias, out, write_idx);
}